// round 1
// baseline (speedup 1.0000x reference)
#include <cuda_runtime.h>
#include <math.h>
#include <stdint.h>

// NetVLAD fused kernel, fp32 CUDA-core baseline.
// B=32, C=128, N=16384 (H*W), K=64.
//
// Kernel 1 (netvlad_main): per (batch, n-tile) CTA:
//   chunked over 64 descriptors: GEMM1 logits = W @ x  -> relu -> softmax over K
//   -> GEMM2 rank-update V[k][c] += a[k][n] x[c][n], asum[k] += a[k][n]
//   Writes per-CTA partials (no atomics -> deterministic).
// Kernel 2 (netvlad_finalize): ordered reduce partials, subtract asum*centroid,
//   intra L2 norm (per k row), global L2 norm (per batch), write output.

#define B_ 32
#define C_ 128
#define N_ 16384
#define K_ 64
#define TILES 32
#define TILE_N (N_ / TILES)      // 512 descriptors per CTA
#define CHUNK 64
#define NCHUNKS (TILE_N / CHUNK) // 8
#define THREADS 256

#define WT_STRIDE 68
#define XS_STRIDE 68
#define XST_STRIDE 132
#define LS_STRIDE 68

#define SMEM_FLOATS (128 * WT_STRIDE + 128 * XS_STRIDE + 64 * XST_STRIDE + 64 * LS_STRIDE + 64)
#define SMEM_BYTES (SMEM_FLOATS * 4)

// Scratch (overwritten fully every launch; no zero-init needed).
__device__ float g_partV[(size_t)B_ * TILES * K_ * C_];  // 33.5 MB
__device__ float g_partA[B_ * TILES * K_];

__global__ __launch_bounds__(THREADS, 1)
void netvlad_main(const float* __restrict__ x,
                  const float* __restrict__ conv_w,
                  const float* __restrict__ conv_b) {
    extern __shared__ float smem[];
    float* Wt  = smem;                       // [c][k], stride 68
    float* Xs  = Wt + 128 * WT_STRIDE;       // [c][n], stride 68
    float* XsT = Xs + 128 * XS_STRIDE;       // [n][c], stride 132
    float* Ls  = XsT + 64 * XST_STRIDE;      // [n][k], stride 68 (logits -> a)
    float* bs  = Ls + 64 * LS_STRIDE;        // [k]

    const int tid  = threadIdx.x;
    const int tile = blockIdx.x;
    const int b    = blockIdx.y;

    // ---- Stage conv_w (coalesced) into Xs scratch, then transpose into Wt[c][k]
    {
        const float4* w4 = reinterpret_cast<const float4*>(conv_w);
        float4* xs4 = reinterpret_cast<float4*>(Xs);
#pragma unroll
        for (int i = 0; i < 8; i++) {
            int idx = tid + i * THREADS;      // 2048 float4 = 8192 floats
            xs4[idx] = __ldg(w4 + idx);
        }
        if (tid < K_) bs[tid] = __ldg(conv_b + tid);
    }
    __syncthreads();
#pragma unroll
    for (int i = 0; i < 32; i++) {
        int idx = tid + i * THREADS;
        int k = idx >> 7;
        int c = idx & 127;
        Wt[c * WT_STRIDE + k] = Xs[idx];
    }
    // sync at top of chunk loop protects Xs reuse

    const int kg = tid & 15;   // k-group of 4 (both GEMMs)
    const int gg = tid >> 4;   // n-group of 4 (GEMM1) / c-group of 8 (GEMM2)

    float Vacc[4][8];
#pragma unroll
    for (int i = 0; i < 4; i++)
#pragma unroll
        for (int j = 0; j < 8; j++) Vacc[i][j] = 0.f;
    float as0 = 0.f, as1 = 0.f, as2 = 0.f, as3 = 0.f;

    const float* xb = x + (size_t)b * C_ * N_ + (size_t)tile * TILE_N;

    for (int ch = 0; ch < NCHUNKS; ch++) {
        const int n0 = ch * CHUNK;
        __syncthreads();   // previous iteration's GEMM2 done with Ls/XsT; Wt transpose done with Xs

        // ---- Load x chunk: 128 c x 64 n, into both layouts
#pragma unroll
        for (int i = 0; i < 8; i++) {
            int idx = tid + i * THREADS;
            int c  = idx >> 4;
            int nq = idx & 15;
            float4 v = __ldg(reinterpret_cast<const float4*>(xb + c * N_ + n0 + nq * 4));
            *reinterpret_cast<float4*>(Xs + c * XS_STRIDE + nq * 4) = v;
            float* xt = XsT + (nq * 4) * XST_STRIDE + c;
            xt[0 * XST_STRIDE] = v.x;
            xt[1 * XST_STRIDE] = v.y;
            xt[2 * XST_STRIDE] = v.z;
            xt[3 * XST_STRIDE] = v.w;
        }
        __syncthreads();

        // ---- GEMM1: L[64k x 64n] = Wt^T @ Xs, 4x4 per thread
        float acc[4][4];
#pragma unroll
        for (int i = 0; i < 4; i++)
#pragma unroll
            for (int j = 0; j < 4; j++) acc[i][j] = 0.f;

#pragma unroll 8
        for (int c = 0; c < 128; c++) {
            float4 wv = *reinterpret_cast<const float4*>(Wt + c * WT_STRIDE + kg * 4);
            float4 xv = *reinterpret_cast<const float4*>(Xs + c * XS_STRIDE + gg * 4);
            float wa[4] = {wv.x, wv.y, wv.z, wv.w};
            float xa[4] = {xv.x, xv.y, xv.z, xv.w};
#pragma unroll
            for (int i = 0; i < 4; i++)
#pragma unroll
                for (int j = 0; j < 4; j++)
                    acc[i][j] += wa[i] * xa[j];
        }

        // bias + relu -> Ls[n][k]
#pragma unroll
        for (int i = 0; i < 4; i++) {
            float bv = bs[kg * 4 + i];
#pragma unroll
            for (int j = 0; j < 4; j++) {
                Ls[(gg * 4 + j) * LS_STRIDE + kg * 4 + i] = fmaxf(acc[i][j] + bv, 0.f);
            }
        }
        __syncthreads();

        // ---- Softmax over k for each n (4 threads per column, 16 k each)
        {
            const int n = tid >> 2;
            const int part = tid & 3;
            float* row = Ls + n * LS_STRIDE + part * 16;
            float v[16];
            float m = 0.f;   // post-relu values are >= 0, so 0 is a valid max seed
#pragma unroll
            for (int t = 0; t < 16; t++) { v[t] = row[t]; m = fmaxf(m, v[t]); }
            m = fmaxf(m, __shfl_xor_sync(0xffffffffu, m, 1));
            m = fmaxf(m, __shfl_xor_sync(0xffffffffu, m, 2));
            float s = 0.f;
#pragma unroll
            for (int t = 0; t < 16; t++) { v[t] = __expf(v[t] - m); s += v[t]; }
            s += __shfl_xor_sync(0xffffffffu, s, 1);
            s += __shfl_xor_sync(0xffffffffu, s, 2);
            const float inv = __fdividef(1.f, s);   // s >= 1 always
#pragma unroll
            for (int t = 0; t < 16; t++) row[t] = v[t] * inv;
        }
        __syncthreads();

        // ---- GEMM2: V[64k x 128c] += A(64x64) @ XsT(64x128), 4x8 per thread
#pragma unroll 8
        for (int n = 0; n < CHUNK; n++) {
            float4 a4 = *reinterpret_cast<const float4*>(Ls + n * LS_STRIDE + kg * 4);
            float4 x0 = *reinterpret_cast<const float4*>(XsT + n * XST_STRIDE + gg * 8);
            float4 x1 = *reinterpret_cast<const float4*>(XsT + n * XST_STRIDE + gg * 8 + 4);
            float av[4] = {a4.x, a4.y, a4.z, a4.w};
            float xv[8] = {x0.x, x0.y, x0.z, x0.w, x1.x, x1.y, x1.z, x1.w};
#pragma unroll
            for (int i = 0; i < 4; i++)
#pragma unroll
                for (int j = 0; j < 8; j++)
                    Vacc[i][j] += av[i] * xv[j];
            if (gg == 0) { as0 += a4.x; as1 += a4.y; as2 += a4.z; as3 += a4.w; }
        }
    }

    // ---- Write per-CTA partials (full overwrite; deterministic)
    {
        float* pV = g_partV + (size_t)(b * TILES + tile) * (K_ * C_);
#pragma unroll
        for (int i = 0; i < 4; i++) {
            int k = kg * 4 + i;
            float4* dst = reinterpret_cast<float4*>(pV + k * C_ + gg * 8);
            dst[0] = make_float4(Vacc[i][0], Vacc[i][1], Vacc[i][2], Vacc[i][3]);
            dst[1] = make_float4(Vacc[i][4], Vacc[i][5], Vacc[i][6], Vacc[i][7]);
        }
        if (gg == 0) {
            float* pA = g_partA + (b * TILES + tile) * K_;
            pA[kg * 4 + 0] = as0;
            pA[kg * 4 + 1] = as1;
            pA[kg * 4 + 2] = as2;
            pA[kg * 4 + 3] = as3;
        }
    }
}

__global__ __launch_bounds__(THREADS, 1)
void netvlad_finalize(const float* __restrict__ centroids, float* __restrict__ out) {
    const int b = blockIdx.x;
    const int tid = threadIdx.x;
    __shared__ float sA[K_];
    __shared__ float rowss[K_];
    __shared__ float gscale_s;

    if (tid < K_) {
        float s = 0.f;
        for (int t = 0; t < TILES; t++) s += g_partA[(b * TILES + t) * K_ + tid];
        sA[tid] = s;
    }
    __syncthreads();

    const int k = tid >> 2;
    const int part = tid & 3;
    const int cbase = part * 32;

    float4 acc[8];
#pragma unroll
    for (int q = 0; q < 8; q++) acc[q] = make_float4(0.f, 0.f, 0.f, 0.f);

    for (int t = 0; t < TILES; t++) {   // fixed order -> deterministic
        const float4* p = reinterpret_cast<const float4*>(
            g_partV + ((size_t)(b * TILES + t) * K_ + k) * C_ + cbase);
#pragma unroll
        for (int q = 0; q < 8; q++) {
            float4 v = p[q];
            acc[q].x += v.x; acc[q].y += v.y; acc[q].z += v.z; acc[q].w += v.w;
        }
    }

    const float ak = sA[k];
    const float4* cen = reinterpret_cast<const float4*>(centroids + k * C_ + cbase);
    float ss = 0.f;
#pragma unroll
    for (int q = 0; q < 8; q++) {
        float4 c4 = __ldg(cen + q);
        acc[q].x -= ak * c4.x; acc[q].y -= ak * c4.y;
        acc[q].z -= ak * c4.z; acc[q].w -= ak * c4.w;
        ss += acc[q].x * acc[q].x + acc[q].y * acc[q].y
            + acc[q].z * acc[q].z + acc[q].w * acc[q].w;
    }
    ss += __shfl_xor_sync(0xffffffffu, ss, 1);
    ss += __shfl_xor_sync(0xffffffffu, ss, 2);
    const float scale = 1.f / fmaxf(sqrtf(ss), 1e-12f);

    float wss = 0.f;
#pragma unroll
    for (int q = 0; q < 8; q++) {
        acc[q].x *= scale; acc[q].y *= scale; acc[q].z *= scale; acc[q].w *= scale;
        wss += acc[q].x * acc[q].x + acc[q].y * acc[q].y
             + acc[q].z * acc[q].z + acc[q].w * acc[q].w;
    }
    wss += __shfl_xor_sync(0xffffffffu, wss, 1);
    wss += __shfl_xor_sync(0xffffffffu, wss, 2);
    if (part == 0) rowss[k] = wss;
    __syncthreads();

    if (tid == 0) {
        float tot = 0.f;
        for (int kk = 0; kk < K_; kk++) tot += rowss[kk];   // fixed order
        gscale_s = 1.f / fmaxf(sqrtf(tot), 1e-12f);
    }
    __syncthreads();

    const float g = gscale_s;
    float4* o = reinterpret_cast<float4*>(out + (size_t)b * K_ * C_ + k * C_ + cbase);
#pragma unroll
    for (int q = 0; q < 8; q++) {
        o[q] = make_float4(acc[q].x * g, acc[q].y * g, acc[q].z * g, acc[q].w * g);
    }
}

extern "C" void kernel_launch(void* const* d_in, const int* in_sizes, int n_in,
                              void* d_out, int out_size) {
    const float* x      = (const float*)d_in[0];
    const float* conv_w = (const float*)d_in[1];
    const float* conv_b = (const float*)d_in[2];
    const float* cen    = (const float*)d_in[3];
    float* out = (float*)d_out;

    cudaFuncSetAttribute(netvlad_main, cudaFuncAttributeMaxDynamicSharedMemorySize, SMEM_BYTES);

    dim3 grid(TILES, B_);
    netvlad_main<<<grid, THREADS, SMEM_BYTES>>>(x, conv_w, conv_b);
    netvlad_finalize<<<B_, THREADS>>>(cen, out);
}

// round 5
// speedup vs baseline: 1.1963x; 1.1963x over previous
#include <cuda_runtime.h>
#include <math.h>
#include <stdint.h>

// NetVLAD fused, fp32. Resubmit of round-3 source (round-4 bench was a broker
// infra failure; this code never ran). Round-3 change under test: finalize
// shared-memory arrays forced to 16B alignment (un-annotated `sv` base was
// 4-mod-16 and float4 loads trapped "misaligned address").
// B=32, C=128, N=16384, K=64.

#define B_ 32
#define C_ 128
#define N_ 16384
#define K_ 64
#define TILES 32
#define TILE_N 512
#define CHUNK 64
#define NCHUNKS 8
#define THREADS 256

#define WT_STRIDE 68
#define XS_STRIDE 68
#define LS_STRIDE 68
#define SMEM_FLOATS (128 * WT_STRIDE + 128 * XS_STRIDE + 64 * LS_STRIDE + 64)
#define SMEM_BYTES (SMEM_FLOATS * 4)

// Scratch (fully overwritten every launch).
__device__ float g_wt[C_ * K_];                               // w^T [c][k]
__device__ float g_partVT[(size_t)B_ * TILES * C_ * K_];      // V^T partials [c][k]
__device__ float g_partA[B_ * TILES * K_];

__global__ void netvlad_prep(const float* __restrict__ w) {
    int idx = blockIdx.x * 1024 + threadIdx.x;   // 8192 total
    int c = idx >> 6, k = idx & 63;
    g_wt[idx] = w[k * C_ + c];
}

__global__ void netvlad_nop() {}   // pads launch sequence so ncu -s 5 hits main

__global__ __launch_bounds__(THREADS, 2)
void netvlad_main(const float* __restrict__ x, const float* __restrict__ conv_b) {
    extern __shared__ float smem[];
    float* Wt = smem;                     // [c][k]  128 x 68
    float* Xs = Wt + 128 * WT_STRIDE;     // [c][n]  128 x 68
    float* Ls = Xs + 128 * XS_STRIDE;     // [n][k]   64 x 68
    float* bs = Ls + 64 * LS_STRIDE;      // [k]

    const int tid  = threadIdx.x;
    const int tile = blockIdx.x;
    const int b    = blockIdx.y;
    const float* xb = x + (size_t)b * C_ * N_ + (size_t)tile * TILE_N;

    const int c0 = tid >> 4;     // 0..15
    const int nq = tid & 15;     // 0..15

    // ---- prefetch chunk 0 into registers (issue before anything else)
    float4 px[8];
#pragma unroll
    for (int i = 0; i < 8; i++)
        px[i] = __ldg(reinterpret_cast<const float4*>(xb + (size_t)(c0 + i * 16) * N_ + nq * 4));

    // ---- load Wt (coalesced from pre-transposed g_wt) + bias
    {
        const float4* wg4 = reinterpret_cast<const float4*>(g_wt);
#pragma unroll
        for (int i = 0; i < 8; i++) {
            int idx = tid + i * THREADS;          // 2048 float4
            float4 v = wg4[idx];
            int c = idx >> 4, kq = idx & 15;
            *reinterpret_cast<float4*>(Wt + c * WT_STRIDE + kq * 4) = v;
        }
        if (tid < K_) bs[tid] = __ldg(conv_b + tid);
    }

    // ---- store chunk-0 prefetch into Xs
#pragma unroll
    for (int i = 0; i < 8; i++)
        *reinterpret_cast<float4*>(Xs + (c0 + i * 16) * XS_STRIDE + nq * 4) = px[i];

    __syncthreads();   // Wt, bs, Xs(chunk 0) visible

    const int kg = tid & 15;     // 4 k's: kg*4..kg*4+3
    const int gg = tid >> 4;     // GEMM1: 4 n's gg*4..; GEMM2: 8 c's gg+16j

    float bias[4];
#pragma unroll
    for (int i = 0; i < 4; i++) bias[i] = bs[kg * 4 + i];

    float Vacc[4][8];
#pragma unroll
    for (int i = 0; i < 4; i++)
#pragma unroll
        for (int j = 0; j < 8; j++) Vacc[i][j] = 0.f;
    float as[4] = {0.f, 0.f, 0.f, 0.f};

    for (int ch = 0; ch < NCHUNKS; ch++) {
        // ---- GEMM1: L[n][k] for 64n x 64k, 4x4 per thread
        float acc[4][4];
#pragma unroll
        for (int i = 0; i < 4; i++)
#pragma unroll
            for (int j = 0; j < 4; j++) acc[i][j] = 0.f;

#pragma unroll 8
        for (int c = 0; c < 128; c++) {
            float4 wv = *reinterpret_cast<const float4*>(Wt + c * WT_STRIDE + kg * 4);
            float4 xv = *reinterpret_cast<const float4*>(Xs + c * XS_STRIDE + gg * 4);
            float wa[4] = {wv.x, wv.y, wv.z, wv.w};
            float xa[4] = {xv.x, xv.y, xv.z, xv.w};
#pragma unroll
            for (int i = 0; i < 4; i++)
#pragma unroll
                for (int j = 0; j < 4; j++)
                    acc[i][j] += wa[i] * xa[j];
        }
        // bias + relu, float4-along-k stores (conflict-free)
#pragma unroll
        for (int j = 0; j < 4; j++) {
            float4 o;
            o.x = fmaxf(acc[0][j] + bias[0], 0.f);
            o.y = fmaxf(acc[1][j] + bias[1], 0.f);
            o.z = fmaxf(acc[2][j] + bias[2], 0.f);
            o.w = fmaxf(acc[3][j] + bias[3], 0.f);
            *reinterpret_cast<float4*>(Ls + (gg * 4 + j) * LS_STRIDE + kg * 4) = o;
        }
        __syncthreads();

        // ---- softmax over k (4 threads per descriptor, 16 k each)
        {
            const int n = tid >> 2;
            const int part = tid & 3;
            float* row = Ls + n * LS_STRIDE + part * 16;
            float v[16];
            float m = 0.f;   // post-relu >= 0
#pragma unroll
            for (int t = 0; t < 16; t++) { v[t] = row[t]; m = fmaxf(m, v[t]); }
            m = fmaxf(m, __shfl_xor_sync(0xffffffffu, m, 1));
            m = fmaxf(m, __shfl_xor_sync(0xffffffffu, m, 2));
            float s = 0.f;
#pragma unroll
            for (int t = 0; t < 16; t++) { v[t] = __expf(v[t] - m); s += v[t]; }
            s += __shfl_xor_sync(0xffffffffu, s, 1);
            s += __shfl_xor_sync(0xffffffffu, s, 2);
            const float inv = __fdividef(1.f, s);
#pragma unroll
            for (int t = 0; t < 16; t++) row[t] = v[t] * inv;
        }
        __syncthreads();

        // ---- issue prefetch for next chunk (covered by GEMM2 compute)
        const bool pf = (ch + 1 < NCHUNKS);
        if (pf) {
            const int n0 = (ch + 1) * CHUNK;
#pragma unroll
            for (int i = 0; i < 8; i++)
                px[i] = __ldg(reinterpret_cast<const float4*>(
                    xb + (size_t)(c0 + i * 16) * N_ + n0 + nq * 4));
        }

        // ---- GEMM2: V[k][c] += a[k][n] x[c][n]; c = gg + 16j; n-pairs
#pragma unroll 4
        for (int n = 0; n < CHUNK; n += 2) {
            float4 a0 = *reinterpret_cast<const float4*>(Ls + n * LS_STRIDE + kg * 4);
            float4 a1 = *reinterpret_cast<const float4*>(Ls + (n + 1) * LS_STRIDE + kg * 4);
            float2 xc[8];
#pragma unroll
            for (int j = 0; j < 8; j++)
                xc[j] = *reinterpret_cast<const float2*>(Xs + (gg + 16 * j) * XS_STRIDE + n);
            float a0v[4] = {a0.x, a0.y, a0.z, a0.w};
            float a1v[4] = {a1.x, a1.y, a1.z, a1.w};
#pragma unroll
            for (int i = 0; i < 4; i++)
#pragma unroll
                for (int j = 0; j < 8; j++)
                    Vacc[i][j] += a0v[i] * xc[j].x + a1v[i] * xc[j].y;
            if (gg == 0) {
#pragma unroll
                for (int i = 0; i < 4; i++) as[i] += a0v[i] + a1v[i];
            }
        }
        __syncthreads();   // everyone done reading Xs/Ls

        if (pf) {
#pragma unroll
            for (int i = 0; i < 8; i++)
                *reinterpret_cast<float4*>(Xs + (c0 + i * 16) * XS_STRIDE + nq * 4) = px[i];
        }
        __syncthreads();   // Xs(ch+1) visible
    }

    // ---- write V^T partials [c][k], float4 over k (coalesced)
    {
        float* pVT = g_partVT + (size_t)(b * TILES + tile) * (C_ * K_);
#pragma unroll
        for (int j = 0; j < 8; j++) {
            int c = gg + 16 * j;
            *reinterpret_cast<float4*>(pVT + c * K_ + kg * 4) =
                make_float4(Vacc[0][j], Vacc[1][j], Vacc[2][j], Vacc[3][j]);
        }
        if (gg == 0)
            *reinterpret_cast<float4*>(g_partA + (b * TILES + tile) * K_ + kg * 4) =
                make_float4(as[0], as[1], as[2], as[3]);
    }
}

__global__ __launch_bounds__(1024, 1)
void netvlad_finalize(const float* __restrict__ cen, float* __restrict__ out) {
    const int b = blockIdx.x;
    const int tid = threadIdx.x;
    const int k = tid & 63;       // cluster
    const int ci = tid >> 6;      // 0..15 ; this thread's c's: ci*8 + q

    // __align__(16): float4 accesses below require 16B base alignment
    // (unaligned sv was the round-3 "misaligned address" trap).
    __shared__ __align__(16) float sAsum[64];
    __shared__ __align__(16) float sRow[16][64];
    __shared__ __align__(16) float sScale[64];
    __shared__ __align__(16) float sW[64];
    __shared__ __align__(16) float sv[64][132];
    __shared__ float sGs;

    if (tid < 64) {
        float s = 0.f;
#pragma unroll 8
        for (int t = 0; t < TILES; t++) s += g_partA[(b * TILES + t) * K_ + tid];
        sAsum[tid] = s;
    }

    // ordered reduce of V^T partials (coalesced: consecutive k per warp)
    float acc[8];
#pragma unroll
    for (int q = 0; q < 8; q++) acc[q] = 0.f;
    const float* base = g_partVT + (size_t)b * TILES * C_ * K_ + (size_t)(ci * 8) * K_ + k;
    for (int t = 0; t < TILES; t++) {
        const float* p = base + (size_t)t * C_ * K_;
#pragma unroll
        for (int q = 0; q < 8; q++) acc[q] += p[q * K_];
    }
    __syncthreads();   // sAsum ready

    const float ak = sAsum[k];
    float rp = 0.f;
#pragma unroll
    for (int q = 0; q < 8; q++) {
        float v = acc[q] - ak * __ldg(cen + k * C_ + ci * 8 + q);
        acc[q] = v;
        rp += v * v;
    }
    sRow[ci][k] = rp;
    __syncthreads();

    if (tid < 64) {
        float ss = 0.f;
#pragma unroll
        for (int i = 0; i < 16; i++) ss += sRow[i][tid];   // fixed order
        float sc = 1.f / fmaxf(sqrtf(ss), 1e-12f);
        sScale[tid] = sc;
        sW[tid] = ss * sc * sc;
    }
    __syncthreads();
    if (tid == 0) {
        float g = 0.f;
        for (int kk = 0; kk < 64; kk++) g += sW[kk];       // fixed order
        sGs = 1.f / fmaxf(sqrtf(g), 1e-12f);
    }
    __syncthreads();

    const float f = sScale[k] * sGs;
#pragma unroll
    for (int q = 0; q < 8; q++) sv[k][ci * 8 + q] = acc[q] * f;
    __syncthreads();

    // coalesced output: thread -> (k2, 8 consecutive c); sv row stride 132
    // floats = 528B (16B multiple), base 16B aligned.
    const int k2 = tid >> 4;
    const int cc = (tid & 15) * 8;
    float4 v0 = *reinterpret_cast<const float4*>(&sv[k2][cc]);
    float4 v1 = *reinterpret_cast<const float4*>(&sv[k2][cc + 4]);
    float4* o = reinterpret_cast<float4*>(out + (size_t)b * K_ * C_ + k2 * C_ + cc);
    o[0] = v0;
    o[1] = v1;
}

extern "C" void kernel_launch(void* const* d_in, const int* in_sizes, int n_in,
                              void* d_out, int out_size) {
    const float* x      = (const float*)d_in[0];
    const float* conv_w = (const float*)d_in[1];
    const float* conv_b = (const float*)d_in[2];
    const float* cen    = (const float*)d_in[3];
    float* out = (float*)d_out;

    cudaFuncSetAttribute(netvlad_main, cudaFuncAttributeMaxDynamicSharedMemorySize, SMEM_BYTES);

    netvlad_prep<<<8, 1024>>>(conv_w);
    dim3 grid(TILES, B_);
    netvlad_main<<<grid, THREADS, SMEM_BYTES>>>(x, conv_b);
    netvlad_finalize<<<B_, 1024>>>(cen, out);
    netvlad_nop<<<1, 1>>>();   // pads period to 4 so ncu -s 5 captures netvlad_main
}